// round 8
// baseline (speedup 1.0000x reference)
#include <cuda_runtime.h>

// PANLoss: block-specialized fused kernel, register-only hot loops.
//  - sim blocks: 6 streams -> 24 register select-accumulators + packed u64 counts
//    (counts unpacked to floats BEFORE any cross-lane reduction — overflow-safe)
//  - dice blocks: 4 streams -> register accumulators
// Inputs: 0 pred_regions f32, 1 regions_gt f32, 2 pred_kernels f32,
//         3 kernels_gt f32, 4 pred_similarities (16,4,640,640) f32,
//         5 text labels i32 [0,8], 6 kernel labels i32 [0,8]
// Output: 5 f32 scalars.

#define HW4    102400
#define NB     16
#define BPBS   40            // sim blocks/batch: 10 iters exact (40 px/thread)
#define BPBD   25            // dice blocks/batch: 16 iters exact
#define NTH    256
#define NSEG   9
#define NACC   45            // 0-8 T2, 9-17 ct, 18-26 K2, 27-35 ck, 36-44 Ssd
#define EPSF   1e-5f
#define NPXF   409600.0f
#define NBLK   ((BPBS + BPBD) * NB)
#define NWARP  (NTH / 32)

__device__ float        g_hist[NB * NACC];   // zero at entry (reset in tail)
__device__ float        g_dice[NB * 8];
__device__ unsigned int g_sem;

__device__ __forceinline__ float tanh_fast(float x) {
    float t;
    asm("tanh.approx.f32 %0, %1;" : "=f"(t) : "f"(x));
    return t;
}
__device__ __forceinline__ float4 ldcg4(const float4* p) {
    float4 v;
    asm volatile("ld.global.cg.v4.f32 {%0,%1,%2,%3}, [%4];"
                 : "=f"(v.x), "=f"(v.y), "=f"(v.z), "=f"(v.w) : "l"(p));
    return v;
}
__device__ __forceinline__ int4 ldcg4i(const int4* p) {
    int4 v;
    asm volatile("ld.global.cg.v4.s32 {%0,%1,%2,%3}, [%4];"
                 : "=r"(v.x), "=r"(v.y), "=r"(v.z), "=r"(v.w) : "l"(p));
    return v;
}

__global__ __launch_bounds__(NTH) void pan_fused(
    const float4* __restrict__ pr, const float4* __restrict__ rg,
    const float4* __restrict__ pk, const float4* __restrict__ kg,
    const float4* __restrict__ sim,
    const int4* __restrict__ tl, const int4* __restrict__ kl,
    float* __restrict__ out)
{
    __shared__ float        s_acc[NWARP][40];
    __shared__ unsigned int s_last;
    const int b   = blockIdx.y;
    const int tid = threadIdx.x;
    const int wid = tid >> 5;
    const int lid = tid & 31;

    if (blockIdx.x < BPBS) {
        // ================= SIM PATH (register accumulators) =================
        const float4* __restrict__ smb = sim + (size_t)b * 4 * HW4;
        const int4*   __restrict__ tlb = tl + (size_t)b * HW4;
        const int4*   __restrict__ klb = kl + (size_t)b * HW4;

        float acc[24];   // [0..8) aT, [8..16) aK, [16..24) aD  (bins 1..8)
        #pragma unroll
        for (int i = 0; i < 24; i++) acc[i] = 0.f;
        unsigned long long ctp = 0ull, ckp = 0ull;  // 9 fields x 7 bits, <=40 px/thread

        int g = blockIdx.x * NTH + tid;
        const int STR = BPBS * NTH;               // 10240

#define SIM_PROC(s0x, s1x, s2x, s3x, tx, kx) do {                              \
        float s2_ = fmaf((s0x),(s0x), fmaf((s1x),(s1x),                        \
                    fmaf((s2x),(s2x), (s3x)*(s3x))));                          \
        float s2d_ = ((tx) == (kx)) ? s2_ : 0.0f;                              \
        _Pragma("unroll")                                                      \
        for (int i_ = 0; i_ < 8; i_++) {                                       \
            acc[i_]      += ((tx) == i_ + 1) ? s2_  : 0.0f;                    \
            acc[8 + i_]  += ((kx) == i_ + 1) ? s2_  : 0.0f;                    \
            acc[16 + i_] += ((tx) == i_ + 1) ? s2d_ : 0.0f;                    \
        }                                                                      \
        ctp += 1ULL << ((tx) * 7);                                             \
        ckp += 1ULL << ((kx) * 7);                                             \
    } while (0)

        #pragma unroll 2
        for (int it = 0; it < 10; it++) {
            float4 S0 = ldcg4(smb + g);
            float4 S1 = ldcg4(smb + HW4 + g);
            float4 S2 = ldcg4(smb + 2 * HW4 + g);
            float4 S3 = ldcg4(smb + 3 * HW4 + g);
            int4   T  = ldcg4i(tlb + g);
            int4   K  = ldcg4i(klb + g);

            SIM_PROC(S0.x, S1.x, S2.x, S3.x, T.x, K.x);
            SIM_PROC(S0.y, S1.y, S2.y, S3.y, T.y, K.y);
            SIM_PROC(S0.z, S1.z, S2.z, S3.z, T.z, K.z);
            SIM_PROC(S0.w, S1.w, S2.w, S3.w, T.w, K.w);
            g += STR;
        }
#undef SIM_PROC

        // ---- unpack per-thread counts to floats (each field <= 40, safe) ----
        float vals[40];
        #pragma unroll
        for (int i = 0; i < 24; i++) vals[i] = acc[i];
        #pragma unroll
        for (int i = 0; i < 8; i++) {
            vals[24 + i] = (float)((unsigned int)(ctp >> (7 * (i + 1))) & 0x7Fu);
            vals[32 + i] = (float)((unsigned int)(ckp >> (7 * (i + 1))) & 0x7Fu);
        }

        // ---- warp-reduce 40 floats ----
        #pragma unroll
        for (int o = 16; o; o >>= 1) {
            #pragma unroll
            for (int i = 0; i < 40; i++)
                vals[i] += __shfl_down_sync(0xffffffffu, vals[i], o);
        }
        if (lid == 0) {
            #pragma unroll
            for (int i = 0; i < 40; i++) s_acc[wid][i] = vals[i];
        }
        __syncthreads();

        // ---- block combine: 40 slots by threads 0..39 ----
        if (tid < 40) {
            float v = 0.f;
            #pragma unroll
            for (int w = 0; w < NWARP; w++) v += s_acc[w][tid];
            int grp = tid >> 3;            // 0:T2 1:K2 2:Ssd 3:ct 4:ck
            int lbl = (tid & 7) + 1;       // bins 1..8
            int slot;
            switch (grp) {
                case 0:  slot = lbl;       break;   // T2
                case 1:  slot = 18 + lbl;  break;   // K2
                case 2:  slot = 36 + lbl;  break;   // Ssd
                case 3:  slot = 9 + lbl;   break;   // ct
                default: slot = 27 + lbl;  break;   // ck
            }
            atomicAdd(&g_hist[b * NACC + slot], v);
        }
    } else {
        // ================= DICE PATH =================
        const int dbx = blockIdx.x - BPBS;
        const float4* __restrict__ prb = pr + (size_t)b * HW4;
        const float4* __restrict__ rgb = rg + (size_t)b * HW4;
        const float4* __restrict__ pkb = pk + (size_t)b * HW4;
        const float4* __restrict__ kgb = kg + (size_t)b * HW4;

        float St_r = 0.f, St2_r = 0.f, Sgt_r = 0.f, Sg_r = 0.f;
        float St_k = 0.f, St2_k = 0.f, Sgt_k = 0.f, Sg_k = 0.f;

        int g = dbx * NTH + tid;
        const int STR = BPBD * NTH;               // 6400

#define DICE_PROC(ax, gx, cx, dx) do {                                         \
        float t1_ = tanh_fast(0.5f * (ax));                                    \
        St_r  += t1_;                                                          \
        St2_r  = fmaf(t1_, t1_, St2_r);                                        \
        Sgt_r  = fmaf(t1_, (gx), Sgt_r);                                       \
        Sg_r  += (gx);                                                         \
        float t2_ = tanh_fast(0.5f * (cx));                                    \
        St_k  += t2_;                                                          \
        St2_k  = fmaf(t2_, t2_, St2_k);                                        \
        Sgt_k  = fmaf(t2_, (dx), Sgt_k);                                       \
        Sg_k  += (dx);                                                         \
    } while (0)

        #pragma unroll 2
        for (int it = 0; it < 16; it++) {
            float4 A = ldcg4(prb + g);
            float4 G = ldcg4(rgb + g);
            float4 C = ldcg4(pkb + g);
            float4 D = ldcg4(kgb + g);

            DICE_PROC(A.x, G.x, C.x, D.x);
            DICE_PROC(A.y, G.y, C.y, D.y);
            DICE_PROC(A.z, G.z, C.z, D.z);
            DICE_PROC(A.w, G.w, C.w, D.w);
            g += STR;
        }
#undef DICE_PROC

        #pragma unroll
        for (int o = 16; o; o >>= 1) {
            St_r  += __shfl_down_sync(0xffffffffu, St_r,  o);
            St2_r += __shfl_down_sync(0xffffffffu, St2_r, o);
            Sgt_r += __shfl_down_sync(0xffffffffu, Sgt_r, o);
            Sg_r  += __shfl_down_sync(0xffffffffu, Sg_r,  o);
            St_k  += __shfl_down_sync(0xffffffffu, St_k,  o);
            St2_k += __shfl_down_sync(0xffffffffu, St2_k, o);
            Sgt_k += __shfl_down_sync(0xffffffffu, Sgt_k, o);
            Sg_k  += __shfl_down_sync(0xffffffffu, Sg_k,  o);
        }
        if (lid == 0) {
            atomicAdd(&g_dice[b*8+0], St_r);  atomicAdd(&g_dice[b*8+1], St2_r);
            atomicAdd(&g_dice[b*8+2], Sgt_r); atomicAdd(&g_dice[b*8+3], Sg_r);
            atomicAdd(&g_dice[b*8+4], St_k);  atomicAdd(&g_dice[b*8+5], St2_k);
            atomicAdd(&g_dice[b*8+6], Sgt_k); atomicAdd(&g_dice[b*8+7], Sg_k);
        }
    }

    __threadfence();
    __syncthreads();
    if (tid == 0)
        s_last = (atomicAdd(&g_sem, 1u) == (unsigned)(NBLK - 1)) ? 1u : 0u;
    __syncthreads();
    if (!s_last) return;

    // ---------------- finalize (last block only) ----------------
    __threadfence();

    float lr = 0.f, lk = 0.f, lagg = 0.f, ldis = 0.f;
    if (tid < NB) {
        float T2[NSEG], ct[NSEG], K2[NSEG], ck[NSEG], Ssd[NSEG], a[8];
        #pragma unroll
        for (int i = 0; i < NSEG; i++) {
            T2[i]  = g_hist[tid * NACC + i];
            ct[i]  = g_hist[tid * NACC + 9 + i];
            K2[i]  = g_hist[tid * NACC + 18 + i];
            ck[i]  = g_hist[tid * NACC + 27 + i];
            Ssd[i] = g_hist[tid * NACC + 36 + i];
        }

        float St  = g_dice[tid*8+0], St2 = g_dice[tid*8+1];
        float Sgt = g_dice[tid*8+2], Sg  = g_dice[tid*8+3];
        float I = 0.5f * (Sgt + Sg);
        float P = 0.25f * (NPXF + 2.f * St + St2);
        lr = 1.0f - (2.0f * I + EPSF) / ((P + EPSF) + (Sg + EPSF));

        St  = g_dice[tid*8+4]; St2 = g_dice[tid*8+5];
        Sgt = g_dice[tid*8+6]; Sg  = g_dice[tid*8+7];
        I = 0.5f * (Sgt + Sg);
        P = 0.25f * (NPXF + 2.f * St + St2);
        lk = 1.0f - (2.0f * I + EPSF) / ((P + EPSF) + (Sg + EPSF));

        #pragma unroll 1
        for (int i = 1; i < NSEG; i++) {
            float inv = 1.0f / (ck[i] + 1.0f);
            float n2  = T2[i] - (2.0f * inv - inv * inv) * Ssd[i]
                        + inv * inv * (K2[i] - Ssd[i]);
            float nrm = sqrtf(fmaxf(n2, 0.0f));
            float d   = nrm - 0.5f;                    // SIGMA_AGG (no clamp)
            lagg += logf(d * d + 1.0f) / (ct[i] + 1.0f);
            float c1 = ck[i] + 0.001f;
            a[i - 1] = K2[i] / (c1 * c1);
        }
        #pragma unroll 1
        for (int i = 0; i < 8; i++)
            #pragma unroll 1
            for (int j = i + 1; j < 8; j++) {
                float pr_ = 3.0f - sqrtf(a[i] + a[j]); // SIGMA_DIS
                ldis += logf(pr_ * pr_ + 1.0f);
            }
        ldis *= (1.0f / 56.0f);
    }

    if (tid < 32) {
        #pragma unroll
        for (int o = 16; o; o >>= 1) {
            lr   += __shfl_down_sync(0xffffffffu, lr,   o);
            lk   += __shfl_down_sync(0xffffffffu, lk,   o);
            lagg += __shfl_down_sync(0xffffffffu, lagg, o);
            ldis += __shfl_down_sync(0xffffffffu, ldis, o);
        }
        if (tid == 0) {
            out[0] = lr + 0.5f * lk + 0.25f * (lagg + ldis);  // ALPHA, BETA
            out[1] = lr;
            out[2] = lk;
            out[3] = lagg;
            out[4] = ldis;
        }
    }
    __syncthreads();

    // reset scratch for next graph replay
    for (int i = tid; i < NB * NACC; i += NTH) g_hist[i] = 0.f;
    for (int i = tid; i < NB * 8;    i += NTH) g_dice[i] = 0.f;
    __threadfence();
    __syncthreads();
    if (tid == 0) g_sem = 0u;
}

extern "C" void kernel_launch(void* const* d_in, const int* in_sizes, int n_in,
                              void* d_out, int out_size) {
    (void)in_sizes; (void)n_in; (void)out_size;
    dim3 grid(BPBS + BPBD, NB);
    pan_fused<<<grid, NTH>>>(
        (const float4*)d_in[0], (const float4*)d_in[1],
        (const float4*)d_in[2], (const float4*)d_in[3],
        (const float4*)d_in[4],
        (const int4*)d_in[5],  (const int4*)d_in[6],
        (float*)d_out);
}